// round 6
// baseline (speedup 1.0000x reference)
#include <cuda_runtime.h>
#include <cstdint>
#include <math.h>

// Problem constants (fixed by the dataset problem)
#define BATCH  16
#define NPTS   6890
#define NBUCK  2048
#define BSCALE 128.0f          // buckets per unit x: range [-8, 8) -> 2048
#define BOFF   8.0f
#define BSTRIDE 256            // bound sampling stride (~27 samples per row)

// k1/k3 geometry
#define TPB1    1024
#define BPB1    7              // 7 * 1024 = 7168 >= 6890
// k4 geometry
#define TPB4    256
#define RPW     4              // rows per warp
#define ROWS_PB4 (8 * RPW)     // 8 warps * 4 = 32 rows per block
#define BPB4    216            // 216 * 32 = 6912 >= 6890
#define NBLK4   (BPB4 * BATCH) // 3456

// ---- persistent device state (static globals; no allocation) ----
// Entry invariant (restored every run): g_hist == 0, g_arr == 0,
// g_bound_i == g_min_i == +inf bits.
__device__ int    g_hist[BATCH][NBUCK];          // zero-init; k2 re-zeroes
__device__ int    g_bstart[BATCH][NBUCK + 1];
__device__ int    g_cursor[BATCH][NBUCK];
__device__ float4 g_p2[BATCH][NPTS];             // sorted v2: (x, y, z, ||q||^2)
__device__ int    g_bound_i = 0x7F800000;        // +inf bits (k4 resets)
__device__ int    g_min_i   = 0x7F800000;        // +inf bits (k4 resets)
__device__ int    g_arr;                         // zero-init (k4 resets)

__device__ __forceinline__ int bucket_of(float x) {
    int b = (int)((x + BOFF) * BSCALE);          // monotone map
    return min(max(b, 0), NBUCK - 1);
}

// ============================================================
// k1: v2.x histogram + sampled upper bound on min squared dist
// ============================================================
__global__ __launch_bounds__(TPB1) void k1_hist_bound(
    const float* __restrict__ v1, const float* __restrict__ v2)
{
    const int b = blockIdx.y;
    const int i = blockIdx.x * TPB1 + threadIdx.x;
    const int lane = threadIdx.x & 31;

    if (i < NPTS) {
        float x = v2[((size_t)b * NPTS + i) * 3];
        atomicAdd(&g_hist[b][bucket_of(x)], 1);
    }

    float vmin = INFINITY;                        // inactive lanes contribute INF
    if (i < NPTS) {
        const float* p = v1 + ((size_t)b * NPTS + i) * 3;
        float x = p[0], y = p[1], z = p[2];
        float pn = fmaf(z, z, fmaf(y, y, x * x));
        float nx = -2.f * x, ny = -2.f * y, nz = -2.f * z;
        // warp-uniform phase -> all lanes load the same q (smem-free broadcast)
        int phase = ((blockIdx.x * 97 + (threadIdx.x >> 5) * 31) ^ (b * 13)) & (BSTRIDE - 1);
        float m = INFINITY;
        for (int j = phase; j < NPTS; j += BSTRIDE) {
            const float* q = v2 + ((size_t)b * NPTS + j) * 3;
            float qx = q[0], qy = q[1], qz = q[2];
            float qn = fmaf(qz, qz, fmaf(qy, qy, qx * qx));
            float d = fmaf(nx, qx, qn);
            d = fmaf(ny, qy, d);
            d = fmaf(nz, qz, d);
            m = fminf(m, d);
        }
        vmin = pn + m;
    }
    // FULL-warp reduction (no divergent shfl!)
#pragma unroll
    for (int o = 16; o; o >>= 1)
        vmin = fminf(vmin, __shfl_xor_sync(0xFFFFFFFFu, vmin, o));
    if (lane == 0 && vmin < INFINITY)
        atomicMin(&g_bound_i, __float_as_int(vmin));
}

// ============================================================
// k2: per-batch exclusive scan of histogram; zero hist behind
// ============================================================
__global__ __launch_bounds__(1024) void k2_scan()
{
    __shared__ int warpsum[32];
    const int b = blockIdx.x;
    const int tid = threadIdx.x, lane = tid & 31, wid = tid >> 5;

    int a0 = g_hist[b][2 * tid], a1 = g_hist[b][2 * tid + 1];
    g_hist[b][2 * tid] = 0; g_hist[b][2 * tid + 1] = 0;   // restore invariant
    int s = a0 + a1;
    int v = s;
#pragma unroll
    for (int o = 1; o < 32; o <<= 1) {
        int t = __shfl_up_sync(0xFFFFFFFFu, v, o);
        if (lane >= o) v += t;
    }
    if (lane == 31) warpsum[wid] = v;
    __syncthreads();
    if (wid == 0) {
        int w = warpsum[lane];
#pragma unroll
        for (int o = 1; o < 32; o <<= 1) {
            int t = __shfl_up_sync(0xFFFFFFFFu, w, o);
            if (lane >= o) w += t;
        }
        warpsum[lane] = w;
    }
    __syncthreads();
    int excl = v - s + ((wid > 0) ? warpsum[wid - 1] : 0);
    g_bstart[b][2 * tid]     = excl;
    g_bstart[b][2 * tid + 1] = excl + a0;
    g_cursor[b][2 * tid]     = excl;
    g_cursor[b][2 * tid + 1] = excl + a0;
    if (tid == 0) g_bstart[b][NBUCK] = NPTS;
}

// ============================================================
// k3: scatter v2 into x-sorted float4 array
// ============================================================
__global__ __launch_bounds__(TPB1) void k3_scatter(const float* __restrict__ v2)
{
    const int b = blockIdx.y;
    const int j = blockIdx.x * TPB1 + threadIdx.x;
    if (j < NPTS) {
        const float* q = v2 + ((size_t)b * NPTS + j) * 3;
        float x = q[0], y = q[1], z = q[2];
        float qn = fmaf(z, z, fmaf(y, y, x * x));
        int pos = atomicAdd(&g_cursor[b][bucket_of(x)], 1);
        g_p2[b][pos] = make_float4(x, y, z, qn);
    }
}

// ============================================================
// k4: warp-cooperative pruned exact pass + output + state reset
// ============================================================
__global__ __launch_bounds__(TPB4) void k4_prune(
    const float* __restrict__ v1, float* __restrict__ out)
{
    const int b = blockIdx.y;
    const int tid = threadIdx.x, lane = tid & 31, wid = tid >> 5;

    float usq = __int_as_float(g_bound_i);        // written by k1 (prev launch)
    // slack: fp32 rounding of dot-form sq + sqrt rounding
    float U = sqrtf(fmaxf(usq, 0.f) + 5e-5f) * 1.0002f;

    float mloc = INFINITY;
#pragma unroll
    for (int r = 0; r < RPW; r++) {
        int row = blockIdx.x * ROWS_PB4 + wid * RPW + r;
        if (row < NPTS) {
            const float* p = v1 + ((size_t)b * NPTS + row) * 3;  // lane-uniform: broadcast
            float x = p[0], y = p[1], z = p[2];
            float pn = fmaf(z, z, fmaf(y, y, x * x));
            float nx = -2.f * x, ny = -2.f * y, nz = -2.f * z;
            int lo = g_bstart[b][bucket_of(x - U)];
            int hi = g_bstart[b][bucket_of(x + U) + 1];
            float md = INFINITY;
            for (int t = lo + lane; t < hi; t += 32) {           // coalesced LDG.128
                float4 q = g_p2[b][t];
                float d = fmaf(nx, q.x, q.w);
                d = fmaf(ny, q.y, d);
                d = fmaf(nz, q.z, d);
                md = fminf(md, d);
            }
            mloc = fminf(mloc, pn + md);
        }
    }

    // FULL-warp reduce, then block reduce
#pragma unroll
    for (int o = 16; o; o >>= 1)
        mloc = fminf(mloc, __shfl_xor_sync(0xFFFFFFFFu, mloc, o));
    __shared__ float smin[TPB4 / 32];
    if (lane == 0) smin[wid] = mloc;
    __syncthreads();
    if (tid == 0) {
        float t = smin[0];
#pragma unroll
        for (int w = 1; w < TPB4 / 32; w++) t = fminf(t, smin[w]);
        if (t < INFINITY)
            atomicMin(&g_min_i, __float_as_int(t));
        __threadfence();
        int a = atomicAdd(&g_arr, 1);
        if (a == NBLK4 - 1) {                     // last block: emit + reset
            int mb = atomicAdd(&g_min_i, 0);      // coherent read
            out[0] = sqrtf(fmaxf(__int_as_float(mb), 0.f));
            g_min_i   = 0x7F800000;
            g_bound_i = 0x7F800000;
            g_arr = 0;
        }
    }
}

extern "C" void kernel_launch(void* const* d_in, const int* in_sizes, int n_in,
                              void* d_out, int out_size)
{
    const float* v1 = (const float*)d_in[0];
    const float* v2 = (const float*)d_in[1];
    float* out = (float*)d_out;

    dim3 g1(BPB1, BATCH);
    k1_hist_bound<<<g1, TPB1>>>(v1, v2);
    k2_scan<<<BATCH, 1024>>>();
    k3_scatter<<<g1, TPB1>>>(v2);
    dim3 g4(BPB4, BATCH);
    k4_prune<<<g4, TPB4>>>(v1, out);
}

// round 8
// speedup vs baseline: 1.1813x; 1.1813x over previous
#include <cuda_runtime.h>
#include <cstdint>
#include <math.h>

// Problem constants (fixed by the dataset problem)
#define BATCH  16
#define NPTS   6890
#define NBUCK  2048
#define BSCALE 128.0f          // buckets per unit x: range [-8, 8) -> 2048
#define BOFF   8.0f

#define TPB    1024
#define BPB    7               // 7 * 1024 = 7168 >= 6890
#define NBLK5  (BPB * BATCH)   // prune grid = 112 blocks

// ---- persistent device state (static globals; no allocation) ----
// Entry invariant (restored every run): g_hist == 0, g_arr == 0,
// g_bound_i == g_min_i == +inf bits.
__device__ int    g_hist[2][BATCH][NBUCK];        // zero-init; k2 re-zeroes
__device__ int    g_bstart[2][BATCH][NBUCK + 1];
__device__ int    g_cursor[2][BATCH][NBUCK];
__device__ float4 g_pts[2][BATCH][NPTS];          // sorted clouds: (x,y,z,||.||^2)
__device__ int    g_bound_i = 0x7F800000;         // +inf bits (k5 resets)
__device__ int    g_min_i   = 0x7F800000;         // +inf bits (k5 resets)
__device__ int    g_arr;                          // zero-init  (k5 resets)

__device__ __forceinline__ int bucket_of(float x) {
    int b = (int)((x + BOFF) * BSCALE);           // monotone map
    return min(max(b, 0), NBUCK - 1);
}

// ============================================================
// k1: x-histogram of both clouds
// ============================================================
__global__ __launch_bounds__(TPB) void k1_hist(
    const float* __restrict__ v1, const float* __restrict__ v2)
{
    const int cloud = blockIdx.z;
    const int b = blockIdx.y;
    const int i = blockIdx.x * TPB + threadIdx.x;
    if (i < NPTS) {
        const float* src = cloud ? v2 : v1;
        float x = src[((size_t)b * NPTS + i) * 3];
        atomicAdd(&g_hist[cloud][b][bucket_of(x)], 1);
    }
}

// ============================================================
// k2: per-(cloud,batch) exclusive scan; zero hist behind itself
// ============================================================
__global__ __launch_bounds__(1024) void k2_scan()
{
    __shared__ int warpsum[32];
    const int b = blockIdx.x, cloud = blockIdx.y;
    const int tid = threadIdx.x, lane = tid & 31, wid = tid >> 5;

    int a0 = g_hist[cloud][b][2 * tid], a1 = g_hist[cloud][b][2 * tid + 1];
    g_hist[cloud][b][2 * tid] = 0; g_hist[cloud][b][2 * tid + 1] = 0;
    int s = a0 + a1;
    int v = s;
#pragma unroll
    for (int o = 1; o < 32; o <<= 1) {
        int t = __shfl_up_sync(0xFFFFFFFFu, v, o);
        if (lane >= o) v += t;
    }
    if (lane == 31) warpsum[wid] = v;
    __syncthreads();
    if (wid == 0) {
        int w = warpsum[lane];
#pragma unroll
        for (int o = 1; o < 32; o <<= 1) {
            int t = __shfl_up_sync(0xFFFFFFFFu, w, o);
            if (lane >= o) w += t;
        }
        warpsum[lane] = w;
    }
    __syncthreads();
    int excl = v - s + ((wid > 0) ? warpsum[wid - 1] : 0);
    g_bstart[cloud][b][2 * tid]     = excl;
    g_bstart[cloud][b][2 * tid + 1] = excl + a0;
    g_cursor[cloud][b][2 * tid]     = excl;
    g_cursor[cloud][b][2 * tid + 1] = excl + a0;
    if (tid == 0) g_bstart[cloud][b][NBUCK] = NPTS;
}

// ============================================================
// k3: scatter both clouds into x-sorted float4 arrays
// ============================================================
__global__ __launch_bounds__(TPB) void k3_scatter(
    const float* __restrict__ v1, const float* __restrict__ v2)
{
    const int cloud = blockIdx.z;
    const int b = blockIdx.y;
    const int i = blockIdx.x * TPB + threadIdx.x;
    if (i < NPTS) {
        const float* src = cloud ? v2 : v1;
        const float* q = src + ((size_t)b * NPTS + i) * 3;
        float x = q[0], y = q[1], z = q[2];
        float qn = fmaf(z, z, fmaf(y, y, x * x));
        int pos = atomicAdd(&g_cursor[cloud][b][bucket_of(x)], 1);
        g_pts[cloud][b][pos] = make_float4(x, y, z, qn);
    }
}

// ============================================================
// k4: tight upper bound via sorted-x neighbors (near-exact)
// ============================================================
__global__ __launch_bounds__(TPB) void k4_bound()
{
    const int b = blockIdx.y;
    const int i = blockIdx.x * TPB + threadIdx.x;

    float vmin = INFINITY;
    if (i < NPTS) {
        float4 p = g_pts[0][b][i];
        float nx = -2.f * p.x, ny = -2.f * p.y, nz = -2.f * p.z;
        int bk = bucket_of(p.x);
        int lo = max(g_bstart[1][b][bk] - 8, 0);
        int hi = min(g_bstart[1][b][bk + 1] + 8, NPTS);
        float m = INFINITY;
        for (int t = lo; t < hi; t++) {
            float4 q = g_pts[1][b][t];
            float d = fmaf(nx, q.x, q.w);
            d = fmaf(ny, q.y, d);
            d = fmaf(nz, q.z, d);
            m = fminf(m, d);
        }
        vmin = p.w + m;
    }
    // full-warp reduce (no divergent shfl)
#pragma unroll
    for (int o = 16; o; o >>= 1)
        vmin = fminf(vmin, __shfl_xor_sync(0xFFFFFFFFu, vmin, o));
    if ((threadIdx.x & 31) == 0 && vmin < INFINITY)
        atomicMin(&g_bound_i, __float_as_int(vmin));
}

// ============================================================
// k5: per-thread pruned exact pass + output + state reset
// ============================================================
__global__ __launch_bounds__(TPB) void k5_prune(float* __restrict__ out)
{
    const int b = blockIdx.y;
    const int i = blockIdx.x * TPB + threadIdx.x;
    const int tid = threadIdx.x, lane = tid & 31, wid = tid >> 5;

    float usq = __int_as_float(g_bound_i);
    // slack covers fp32 dot-form cancellation (<=~1e-5 at these magnitudes)
    float U = sqrtf(fmaxf(usq, 0.f) + 3e-5f) * 1.0005f;

    float vmin = INFINITY;
    if (i < NPTS) {
        float4 p = g_pts[0][b][i];
        float nx = -2.f * p.x, ny = -2.f * p.y, nz = -2.f * p.z;
        int lo = g_bstart[1][b][bucket_of(p.x - U)];
        int hi = g_bstart[1][b][bucket_of(p.x + U) + 1];
        float m = INFINITY;
        for (int t = lo; t < hi; t++) {
            float4 q = g_pts[1][b][t];
            float d = fmaf(nx, q.x, q.w);
            d = fmaf(ny, q.y, d);
            d = fmaf(nz, q.z, d);
            m = fminf(m, d);
        }
        vmin = p.w + m;
    }

#pragma unroll
    for (int o = 16; o; o >>= 1)
        vmin = fminf(vmin, __shfl_xor_sync(0xFFFFFFFFu, vmin, o));
    __shared__ float smin[TPB / 32];
    if (lane == 0) smin[wid] = vmin;
    __syncthreads();
    if (tid == 0) {
        float t = smin[0];
#pragma unroll
        for (int w = 1; w < TPB / 32; w++) t = fminf(t, smin[w]);
        if (t < INFINITY)
            atomicMin(&g_min_i, __float_as_int(t));
        __threadfence();
        int a = atomicAdd(&g_arr, 1);
        if (a == NBLK5 - 1) {                    // last block: emit + reset state
            int mb = atomicAdd(&g_min_i, 0);     // coherent read
            out[0] = sqrtf(fmaxf(__int_as_float(mb), 0.f));
            g_min_i   = 0x7F800000;
            g_bound_i = 0x7F800000;
            g_arr = 0;
        }
    }
}

extern "C" void kernel_launch(void* const* d_in, const int* in_sizes, int n_in,
                              void* d_out, int out_size)
{
    const float* v1 = (const float*)d_in[0];
    const float* v2 = (const float*)d_in[1];
    float* out = (float*)d_out;

    dim3 gh(BPB, BATCH, 2);
    k1_hist<<<gh, TPB>>>(v1, v2);
    dim3 gs(BATCH, 2);
    k2_scan<<<gs, 1024>>>();
    k3_scatter<<<gh, TPB>>>(v1, v2);
    dim3 gp(BPB, BATCH);
    k4_bound<<<gp, TPB>>>();
    k5_prune<<<gp, TPB>>>(out);
}